// round 15
// baseline (speedup 1.0000x reference)
#include <cuda_runtime.h>
#include <math.h>
#include <float.h>

#define NN   10000
#define EE   160000
#define INN  256
#define INE  128
#define CC   64
#define HH   4
#define HCC  256
#define UVSTR 768

// ---------------- scratch (device globals; no allocation allowed) ----------------
__device__ __align__(16) float g_Wcat[256 * 768];          // [K=256][Pni|U|V]
__device__ __align__(16) float g_PUV[(size_t)NN * 768];    // node @ Wcat
__device__ __align__(16) float g_Wc3[INE * HCC];
__device__ __align__(16) float g_nodet[NN * CC];
__device__ __align__(16) float g_bufA[(size_t)EE * HCC];
__device__ __align__(16) float g_bufB[(size_t)EE * HCC];
__device__ __align__(16) float g_em[EE * CC];
__device__ __align__(16) float g_em2[EE * CC];
__device__ __align__(16) float g_sc[EE * HH];
__device__ __align__(16) float g_agg[NN * HCC];
__device__ __align__(16) float g_n0[NN * CC];
__device__ __align__(16) float g_n1[NN * CC];
__device__ __align__(16) float g_deg[NN];
__device__ int g_cnt[NN + 1];
__device__ int g_off[NN + 1];
__device__ int g_cur[NN];
__device__ int g_csr[EE];

// ---------------- helpers ----------------
__device__ __forceinline__ unsigned f2tf(float x) {
    unsigned u;
    asm("cvt.rna.tf32.f32 %0, %1;" : "=r"(u) : "f"(x));
    return u;
}

__device__ __forceinline__ void mma_tf32(float* c, const unsigned* a, const unsigned* b) {
    asm volatile(
        "mma.sync.aligned.m16n8k8.row.col.f32.tf32.tf32.f32 "
        "{%0,%1,%2,%3}, {%4,%5,%6,%7}, {%8,%9}, {%0,%1,%2,%3};"
        : "+f"(c[0]), "+f"(c[1]), "+f"(c[2]), "+f"(c[3])
        : "r"(a[0]), "r"(a[1]), "r"(a[2]), "r"(a[3]), "r"(b[0]), "r"(b[1]));
}

static inline int ceildiv(int a, int b) { return (a + b - 1) / b; }

// =====================================================================
// TF32 tensor-core GEMM with paired-k SMEM layouts (64-bit fragment LDS).
// BM=128, BK=16. Warp tile 32x32 (MT=2, NT=4).
// BN=128: 512 threads (16 warps 4x4). BN=64: 256 threads (8 warps 4x2).
// sA[r][pos]: pos packs (k, k+4) adjacent:  pos(k)=8*(k>>3)+2*(k&3) [k%8<4], +1 for k%8>=4.
// sB2[p][2n]: p = 4*(k>>3)+(k&3) for base k; word pair = (B[k][n], B[k+4][n]).
// Epilogue: bias, COMBINE(+U[dst]+V[src] stride 768), relu, +Cadd.
// =====================================================================
template <int BN, bool RELU, bool HASBIAS, bool COMBINE, bool ADDC>
__global__ __launch_bounds__((BN == 128) ? 512 : 256, (BN == 128) ? 2 : 4)
void mma_gemm(const float* __restrict__ A, const float* __restrict__ B,
              const float* __restrict__ bias, float* __restrict__ C,
              int M, int Ncol, int K,
              const int* __restrict__ srcI, const int* __restrict__ dstI,
              const float* __restrict__ Uv, const float* __restrict__ Vv,
              const float* __restrict__ Cadd)
{
    constexpr int MT = 2;
    constexpr int NT = 4;
    constexpr int SAS = 24;                       // sA row stride (words)
    constexpr int SB2 = (BN == 128) ? 264 : 136;  // sB2 row stride (words)

    __shared__ __align__(16) unsigned sA[2][128][SAS];
    __shared__ __align__(16) unsigned sB2[2][8][SB2];

    const int tid = threadIdx.x;
    const int wid = tid >> 5, lane = tid & 31;
    const int warp_m = (BN == 128) ? (wid >> 2) : (wid >> 1);   // 0..3
    const int warp_n = (BN == 128) ? (wid & 3) : (wid & 1);
    const int row0 = blockIdx.y * 128;
    const int col0 = blockIdx.x * BN;
    const int g = lane >> 2, tg = lane & 3;

    float acc[MT][NT][4];
#pragma unroll
    for (int i = 0; i < MT; i++)
#pragma unroll
        for (int j = 0; j < NT; j++)
#pragma unroll
            for (int q = 0; q < 4; q++) acc[i][j][q] = 0.f;

    const int nk = K >> 4;

    auto store_a = [&](int st, int r, int q, float4 v0, float4 v1) {
        unsigned* dp = &sA[st][r][8 * q];
        uint4 w0 = make_uint4(f2tf(v0.x), f2tf(v1.x), f2tf(v0.y), f2tf(v1.y));
        uint4 w1 = make_uint4(f2tf(v0.z), f2tf(v1.z), f2tf(v0.w), f2tf(v1.w));
        *reinterpret_cast<uint4*>(dp) = w0;
        *reinterpret_cast<uint4*>(dp + 4) = w1;
    };
    auto store_b = [&](int st, int p, int n, float4 lo, float4 hi) {
        unsigned* dp = &sB2[st][p][2 * n];
        uint4 w0 = make_uint4(f2tf(lo.x), f2tf(hi.x), f2tf(lo.y), f2tf(hi.y));
        uint4 w1 = make_uint4(f2tf(lo.z), f2tf(hi.z), f2tf(lo.w), f2tf(hi.w));
        *reinterpret_cast<uint4*>(dp) = w0;
        *reinterpret_cast<uint4*>(dp + 4) = w1;
    };

    auto load_tile = [&](int t, int st) {
        const int k0 = t << 4;
        if (BN == 128) {
            if (tid < 256) {
                int r = tid >> 1, q = tid & 1;
                float4 v0 = make_float4(0.f, 0.f, 0.f, 0.f), v1 = v0;
                if (row0 + r < M) {
                    const float* ap = A + (size_t)(row0 + r) * K + k0 + 8 * q;
                    v0 = *reinterpret_cast<const float4*>(ap);
                    v1 = *reinterpret_cast<const float4*>(ap + 4);
                }
                store_a(st, r, q, v0, v1);
            } else {
                int u = tid - 256;
                int p = u >> 5, n = (u & 31) << 2;
                int kb = ((p >> 2) << 3) | (p & 3);
                const float* bp = B + (size_t)(k0 + kb) * Ncol + col0 + n;
                float4 lo = *reinterpret_cast<const float4*>(bp);
                float4 hi = *reinterpret_cast<const float4*>(bp + 4 * Ncol);
                store_b(st, p, n, lo, hi);
            }
        } else {
            {
                int r = tid >> 1, q = tid & 1;
                float4 v0 = make_float4(0.f, 0.f, 0.f, 0.f), v1 = v0;
                if (row0 + r < M) {
                    const float* ap = A + (size_t)(row0 + r) * K + k0 + 8 * q;
                    v0 = *reinterpret_cast<const float4*>(ap);
                    v1 = *reinterpret_cast<const float4*>(ap + 4);
                }
                store_a(st, r, q, v0, v1);
            }
            if (tid < 128) {
                int p = tid >> 4, n = (tid & 15) << 2;
                int kb = ((p >> 2) << 3) | (p & 3);
                const float* bp = B + (size_t)(k0 + kb) * Ncol + col0 + n;
                float4 lo = *reinterpret_cast<const float4*>(bp);
                float4 hi = *reinterpret_cast<const float4*>(bp + 4 * Ncol);
                store_b(st, p, n, lo, hi);
            }
        }
    };

    load_tile(0, 0);
    __syncthreads();

    for (int t = 0; t < nk; t++) {
        const int cur = t & 1;
        if (t + 1 < nk) load_tile(t + 1, cur ^ 1);
#pragma unroll
        for (int kk8 = 0; kk8 < 2; kk8++) {
            uint2 a2[MT][2], b2[NT];
#pragma unroll
            for (int mt = 0; mt < MT; mt++) {
                int r0 = warp_m * 32 + mt * 16 + g;
                a2[mt][0] = *reinterpret_cast<const uint2*>(&sA[cur][r0][8 * kk8 + 2 * tg]);
                a2[mt][1] = *reinterpret_cast<const uint2*>(&sA[cur][r0 + 8][8 * kk8 + 2 * tg]);
            }
#pragma unroll
            for (int nt = 0; nt < NT; nt++) {
                int n = warp_n * 32 + nt * 8 + g;
                b2[nt] = *reinterpret_cast<const uint2*>(&sB2[cur][4 * kk8 + tg][2 * n]);
            }
#pragma unroll
            for (int mt = 0; mt < MT; mt++) {
                unsigned ar[4] = {a2[mt][0].x, a2[mt][1].x, a2[mt][0].y, a2[mt][1].y};
#pragma unroll
                for (int nt = 0; nt < NT; nt++) {
                    unsigned br[2] = {b2[nt].x, b2[nt].y};
                    mma_tf32(acc[mt][nt], ar, br);
                }
            }
        }
        __syncthreads();
    }

#pragma unroll
    for (int mt = 0; mt < MT; mt++) {
#pragma unroll
        for (int h = 0; h < 2; h++) {
            const int r = row0 + warp_m * 32 + mt * 16 + g + h * 8;
            if (r >= M) continue;
            int s = 0, d = 0;
            if (COMBINE) { s = srcI[r]; d = dstI[r]; }
#pragma unroll
            for (int nt = 0; nt < NT; nt++) {
                const int c = col0 + warp_n * 32 + nt * 8 + tg * 2;
                float2 v = make_float2(acc[mt][nt][2 * h], acc[mt][nt][2 * h + 1]);
                if (HASBIAS) { v.x += bias[c]; v.y += bias[c + 1]; }
                if (COMBINE) {
                    float2 uu = *reinterpret_cast<const float2*>(Uv + (size_t)d * UVSTR + c);
                    float2 vv = *reinterpret_cast<const float2*>(Vv + (size_t)s * UVSTR + c);
                    v.x += uu.x + vv.x; v.y += uu.y + vv.y;
                }
                if (RELU) { v.x = fmaxf(v.x, 0.f); v.y = fmaxf(v.y, 0.f); }
                if (ADDC) {
                    float2 ad = *reinterpret_cast<const float2*>(Cadd + (size_t)r * Ncol + c);
                    v.x += ad.x; v.y += ad.y;
                }
                *reinterpret_cast<float2*>(C + (size_t)r * Ncol + c) = v;
            }
        }
    }
}

// =====================================================================
// Batched tiny fp32 GEMMs for weight pre-combination (3 in one launch).
// =====================================================================
__global__ void k_wc3(const float* __restrict__ Wnj, const float* __restrict__ Wni,
                      const float* __restrict__ Weij, const float* __restrict__ A0W,
                      float* __restrict__ Wcat, float* __restrict__ Wc3)
{
    const float* A; const float* B; float* C; int M, ldC;
    if (blockIdx.z == 0)      { A = Wnj;  B = A0W;             C = Wcat + 256; M = 256; ldC = 768; }
    else if (blockIdx.z == 1) { A = Wni;  B = A0W + 512 * 256; C = Wcat + 512; M = 256; ldC = 768; }
    else                      { A = Weij; B = A0W + 256 * 256; C = Wc3;        M = 128; ldC = 256; }

    const int row0 = blockIdx.y * 64;
    if (row0 >= M) return;
    const int col0 = blockIdx.x * 64;

    __shared__ float sA[16][68];
    __shared__ float sB[16][68];
    const int tid = threadIdx.x;
    const int tx = tid & 15, ty = tid >> 4;
    const int lm = tid >> 2, lk = (tid & 3) * 4;
    const int lkb = tid >> 4, lcb = (tid & 15) * 4;

    float acc[4][4];
#pragma unroll
    for (int i = 0; i < 4; i++)
#pragma unroll
        for (int j = 0; j < 4; j++) acc[i][j] = 0.f;

    for (int k0 = 0; k0 < 256; k0 += 16) {
        float4 av = *reinterpret_cast<const float4*>(A + (size_t)(row0 + lm) * 256 + k0 + lk);
        sA[lk + 0][lm] = av.x; sA[lk + 1][lm] = av.y;
        sA[lk + 2][lm] = av.z; sA[lk + 3][lm] = av.w;
        float4 bv = *reinterpret_cast<const float4*>(B + (size_t)(k0 + lkb) * 256 + col0 + lcb);
        sB[lkb][lcb + 0] = bv.x; sB[lkb][lcb + 1] = bv.y;
        sB[lkb][lcb + 2] = bv.z; sB[lkb][lcb + 3] = bv.w;
        __syncthreads();
#pragma unroll
        for (int k = 0; k < 16; k++) {
            float a[4], b[4];
#pragma unroll
            for (int i = 0; i < 4; i++) a[i] = sA[k][ty + 16 * i];
#pragma unroll
            for (int j = 0; j < 4; j++) b[j] = sB[k][tx + 16 * j];
#pragma unroll
            for (int i = 0; i < 4; i++)
#pragma unroll
                for (int j = 0; j < 4; j++) acc[i][j] = fmaf(a[i], b[j], acc[i][j]);
        }
        __syncthreads();
    }
#pragma unroll
    for (int i = 0; i < 4; i++)
#pragma unroll
        for (int j = 0; j < 4; j++)
            C[(size_t)(row0 + ty + 16 * i) * ldC + col0 + tx + 16 * j] = acc[i][j];
}

__global__ void k_copyWni(const float* __restrict__ Wni, float* __restrict__ Wcat)
{
    int i = blockIdx.x * 256 + threadIdx.x;
    if (i < 256 * 256) Wcat[(size_t)(i >> 8) * 768 + (i & 255)] = Wni[i];
}

// ---------------- CSR build ----------------
__global__ void k_init(int* __restrict__ cnt, float* __restrict__ deg)
{
    int i = blockIdx.x * 256 + threadIdx.x;
    if (i < NN + 1) cnt[i] = 0;
    if (i < NN) deg[i] = 1.f;   // self loop
}

__global__ void k_hist(const int* __restrict__ src, const int* __restrict__ dst,
                       int* __restrict__ cnt, float* __restrict__ deg)
{
    int e = blockIdx.x * 256 + threadIdx.x;
    if (e >= EE) return;
    atomicAdd(&cnt[dst[e]], 1);
    if (src[e] != dst[e]) atomicAdd(&deg[src[e]], 1.f);
}

__global__ void k_scan(const int* __restrict__ cnt, int* __restrict__ off,
                       int* __restrict__ cur)
{
    __shared__ int part[1024];
    const int t = threadIdx.x;
    const int CH = 10;                 // 1024*10 >= NN
    int base = t * CH;
    int loc[CH];
    int s = 0;
#pragma unroll
    for (int i = 0; i < CH; i++) {
        int v = (base + i < NN) ? cnt[base + i] : 0;
        loc[i] = s; s += v;
    }
    part[t] = s;
    __syncthreads();
    for (int d = 1; d < 1024; d <<= 1) {
        int v = (t >= d) ? part[t - d] : 0;
        __syncthreads();
        part[t] += v;
        __syncthreads();
    }
    int pre = (t == 0) ? 0 : part[t - 1];
#pragma unroll
    for (int i = 0; i < CH; i++) {
        if (base + i < NN) {
            off[base + i] = pre + loc[i];
            cur[base + i] = pre + loc[i];
        }
    }
    if (t == 1023) off[NN] = part[1023];
}

__global__ void k_fill(const int* __restrict__ dst, int* __restrict__ cur,
                       int* __restrict__ csr)
{
    int e = blockIdx.x * 256 + threadIdx.x;
    if (e >= EE) return;
    int pos = atomicAdd(&cur[dst[e]], 1);
    csr[pos] = e;
}

__global__ void k_dinv(float* __restrict__ deg)
{
    int i = blockIdx.x * 256 + threadIdx.x;
    if (i < NN) deg[i] = rsqrtf(deg[i]);
}

// ---------------- attention ----------------
__global__ void k_scores(const float* __restrict__ f, const float* __restrict__ attn,
                         const int* __restrict__ dst, float* __restrict__ sc)
{
    int warp = (blockIdx.x * blockDim.x + threadIdx.x) >> 5;
    int lane = threadIdx.x & 31;
    if (warp >= EE) return;
    const float* fr = f + (size_t)warp * HCC;
    int c0 = lane * 8;
    float p = 0.f;
#pragma unroll
    for (int i = 0; i < 8; i++) p = fmaf(fr[c0 + i], attn[c0 + i], p);
    p += __shfl_down_sync(0xffffffffu, p, 4, 8);
    p += __shfl_down_sync(0xffffffffu, p, 2, 8);
    p += __shfl_down_sync(0xffffffffu, p, 1, 8);
    if ((lane & 7) == 0) sc[warp * 4 + (lane >> 3)] = p;
}

// one warp per node: online softmax over in-edges + alpha-weighted aggregation
__global__ void k_node_attn(const int* __restrict__ off, const int* __restrict__ csr,
                            const int* __restrict__ src, const float* __restrict__ sc,
                            const float* __restrict__ lin, const float* __restrict__ Pni,
                            float* __restrict__ agg, float* __restrict__ attnw)
{
    int node = blockIdx.x * 8 + (threadIdx.x >> 5);
    int lane = threadIdx.x & 31;
    if (node >= NN) return;
    const int beg = off[node], end = off[node + 1];

    float m0 = -FLT_MAX, m1 = -FLT_MAX, m2 = -FLT_MAX, m3 = -FLT_MAX;
    float s0 = 0.f, s1 = 0.f, s2 = 0.f, s3 = 0.f;
    for (int i = beg; i < end; i++) {
        int e = csr[i];
        float4 s = *reinterpret_cast<const float4*>(sc + (size_t)e * 4);
        float n0 = fmaxf(m0, s.x); s0 = s0 * __expf(m0 - n0) + __expf(s.x - n0); m0 = n0;
        float n1 = fmaxf(m1, s.y); s1 = s1 * __expf(m1 - n1) + __expf(s.y - n1); m1 = n1;
        float n2 = fmaxf(m2, s.z); s2 = s2 * __expf(m2 - n2) + __expf(s.z - n2); m2 = n2;
        float n3 = fmaxf(m3, s.w); s3 = s3 * __expf(m3 - n3) + __expf(s.w - n3); m3 = n3;
    }
    float r0 = (end > beg) ? 1.f / s0 : 0.f;
    float r1 = (end > beg) ? 1.f / s1 : 0.f;
    float r2 = (end > beg) ? 1.f / s2 : 0.f;
    float r3 = (end > beg) ? 1.f / s3 : 0.f;

    const int h = lane >> 3;
    const float mh = (h == 0) ? m0 : (h == 1) ? m1 : (h == 2) ? m2 : m3;
    const float rh = (h == 0) ? r0 : (h == 1) ? r1 : (h == 2) ? r2 : r3;

    float a0 = 0.f, a1 = 0.f, a2 = 0.f, a3 = 0.f, a4 = 0.f, a5 = 0.f, a6 = 0.f, a7 = 0.f;
    for (int i = beg; i < end; i++) {
        int e = csr[i];
        float4 s = *reinterpret_cast<const float4*>(sc + (size_t)e * 4);
        if (lane == 0) {
            float w = __expf(s.x - m0) * r0 * lin[0] + __expf(s.y - m1) * r1 * lin[1]
                    + __expf(s.z - m2) * r2 * lin[2] + __expf(s.w - m3) * r3 * lin[3];
            attnw[e] = w;
        }
        float sh = (h == 0) ? s.x : (h == 1) ? s.y : (h == 2) ? s.z : s.w;
        float al = __expf(sh - mh) * rh;
        const float4* pr = reinterpret_cast<const float4*>(Pni + (size_t)src[e] * UVSTR + lane * 8);
        float4 p0 = pr[0], p1 = pr[1];
        a0 = fmaf(al, p0.x, a0); a1 = fmaf(al, p0.y, a1);
        a2 = fmaf(al, p0.z, a2); a3 = fmaf(al, p0.w, a3);
        a4 = fmaf(al, p1.x, a4); a5 = fmaf(al, p1.y, a5);
        a6 = fmaf(al, p1.z, a6); a7 = fmaf(al, p1.w, a7);
    }
    float4* ao = reinterpret_cast<float4*>(agg + (size_t)node * HCC + lane * 8);
    ao[0] = make_float4(a0, a1, a2, a3);
    ao[1] = make_float4(a4, a5, a6, a7);
}

// one warp per node: GCN gather
__global__ void k_gcn(const int* __restrict__ off, const int* __restrict__ csr,
                      const int* __restrict__ src, const float* __restrict__ dinv,
                      const float* __restrict__ xg, const float* __restrict__ gb,
                      float* __restrict__ outn)
{
    int node = blockIdx.x * 8 + (threadIdx.x >> 5);
    int lane = threadIdx.x & 31;
    if (node >= NN) return;
    const int beg = off[node], end = off[node + 1];
    const float di = dinv[node];
    float2 x = *reinterpret_cast<const float2*>(xg + (size_t)node * CC + lane * 2);
    float ax = di * di * x.x + gb[lane * 2];
    float ay = di * di * x.y + gb[lane * 2 + 1];
    for (int i = beg; i < end; i++) {
        int e = csr[i];
        int s = src[e];
        if (s == node) continue;
        float c = dinv[s] * di;
        float2 xs = *reinterpret_cast<const float2*>(xg + (size_t)s * CC + lane * 2);
        ax = fmaf(c, xs.x, ax);
        ay = fmaf(c, xs.y, ay);
    }
    *reinterpret_cast<float2*>(outn + (size_t)node * CC + lane * 2) = make_float2(ax, ay);
}

// ---------------- launch ----------------
extern "C" void kernel_launch(void* const* d_in, const int* in_sizes, int n_in,
                              void* d_out, int out_size)
{
    const float* node = (const float*)d_in[0];
    const float* ef   = (const float*)d_in[1];
    const int*   ei   = (const int*)d_in[2];
    const int* src = ei;
    const int* dst = ei + EE;
    const float* W_ni = (const float*)d_in[3];
    const float* W_nj = (const float*)d_in[4];
    const float* W_eij= (const float*)d_in[5];
    const float* W_nt = (const float*)d_in[6];
    const float* b_nt = (const float*)d_in[7];
    const float* W_et = (const float*)d_in[8];
    const float* b_et = (const float*)d_in[9];
    const float* A0W  = (const float*)d_in[10];
    const float* A0b  = (const float*)d_in[11];
    const float* A1W  = (const float*)d_in[12];
    const float* A1b  = (const float*)d_in[13];
    const float* A2W  = (const float*)d_in[14];
    const float* A2b  = (const float*)d_in[15];
    const float* attn = (const float*)d_in[16];
    const float* Nm0W = (const float*)d_in[17];
    const float* Nm0b = (const float*)d_in[18];
    const float* Nm1W = (const float*)d_in[19];
    const float* Nm1b = (const float*)d_in[20];
    const float* Nm2W = (const float*)d_in[21];
    const float* Nm2b = (const float*)d_in[22];
    const float* Em0W = (const float*)d_in[23];
    const float* Em0b = (const float*)d_in[24];
    const float* Em1W = (const float*)d_in[25];
    const float* Em1b = (const float*)d_in[26];
    const float* Em2W = (const float*)d_in[27];
    const float* Em2b = (const float*)d_in[28];
    const float* linW = (const float*)d_in[29];
    const float* gcnW = (const float*)d_in[30];
    const float* gcnb = (const float*)d_in[31];

    float *Wcat, *PUV, *Wc3, *nodet, *bufA, *bufB, *em, *em2, *sc, *agg;
    float *n0, *n1, *deg;
    int *cnt, *off, *cur, *csr;
    cudaGetSymbolAddress((void**)&Wcat, g_Wcat);
    cudaGetSymbolAddress((void**)&PUV,  g_PUV);
    cudaGetSymbolAddress((void**)&Wc3,  g_Wc3);
    cudaGetSymbolAddress((void**)&nodet,g_nodet);
    cudaGetSymbolAddress((void**)&bufA, g_bufA);
    cudaGetSymbolAddress((void**)&bufB, g_bufB);
    cudaGetSymbolAddress((void**)&em,   g_em);
    cudaGetSymbolAddress((void**)&em2,  g_em2);
    cudaGetSymbolAddress((void**)&sc,   g_sc);
    cudaGetSymbolAddress((void**)&agg,  g_agg);
    cudaGetSymbolAddress((void**)&n0,   g_n0);
    cudaGetSymbolAddress((void**)&n1,   g_n1);
    cudaGetSymbolAddress((void**)&deg,  g_deg);
    cudaGetSymbolAddress((void**)&cnt,  g_cnt);
    cudaGetSymbolAddress((void**)&off,  g_off);
    cudaGetSymbolAddress((void**)&cur,  g_cur);
    cudaGetSymbolAddress((void**)&csr,  g_csr);

    float* out_node = (float*)d_out;               // [N,64]
    float* out_edge = out_node + NN * CC;          // [E,64]
    float* out_attn = out_edge + (size_t)EE * CC;  // [E]

    const float* Uv = PUV + 256;   // U region (dst), row stride 768
    const float* Vv = PUV + 512;   // V region (src)

    // 0) CSR build + deg + weight pre-combination
    k_init<<<ceildiv(NN + 1, 256), 256>>>(cnt, deg);
    k_copyWni<<<256, 256>>>(W_ni, Wcat);
    k_wc3<<<dim3(4, 4, 3), 256>>>(W_nj, W_ni, W_eij, A0W, Wcat, Wc3);
    k_hist<<<ceildiv(EE, 256), 256>>>(src, dst, cnt, deg);
    k_scan<<<1, 1024>>>(cnt, off, cur);
    k_fill<<<ceildiv(EE, 256), 256>>>(dst, cur, csr);
    k_dinv<<<ceildiv(NN, 256), 256>>>(deg);

    // 1) node-level projections: PUV = node @ Wcat  ([10000,768])
    mma_gemm<128, false, false, false, false><<<dim3(6, ceildiv(NN, 128)), 512>>>(
        node, Wcat, nullptr, PUV, NN, 768, 256, nullptr, nullptr, nullptr, nullptr, nullptr);
    mma_gemm<64, false, true, false, false><<<dim3(1, ceildiv(NN, 128)), 256>>>(
        node, W_nt, b_nt, nodet, NN, CC, 256, nullptr, nullptr, nullptr, nullptr, nullptr);

    // 2) edge projections; f0 fused: relu(ef@Wc3 + A0b + U[dst] + V[src]) -> bufA
    mma_gemm<128, true, true, true, false><<<dim3(2, EE / 128), 512>>>(
        ef, Wc3, A0b, bufA, EE, HCC, INE, src, dst, Uv, Vv, nullptr);
    mma_gemm<64, false, true, false, false><<<dim3(1, EE / 128), 256>>>(
        ef, W_et, b_et, out_edge, EE, CC, INE, nullptr, nullptr, nullptr, nullptr, nullptr);

    // 3) edge MLP chain (the big GEMMs)
    mma_gemm<128, true, true, false, false><<<dim3(2, EE / 128), 512>>>(
        bufA, A1W, A1b, bufB, EE, HCC, HCC, nullptr, nullptr, nullptr, nullptr, nullptr);
    mma_gemm<128, true, true, false, false><<<dim3(2, EE / 128), 512>>>(
        bufB, A2W, A2b, bufA, EE, HCC, HCC, nullptr, nullptr, nullptr, nullptr, nullptr);

    // 4) attention: scores, then per-node softmax + aggregation (CSR, no atomics)
    k_scores<<<ceildiv(EE * 32, 256), 256>>>(bufA, attn, dst, sc);
    k_node_attn<<<ceildiv(NN, 8), 256>>>(off, csr, src, sc, linW, PUV, agg, out_attn);

    // 5) edge output MLP: out_edge += relu-mlp3(f)
    mma_gemm<64, true, true, false, false><<<dim3(1, EE / 128), 256>>>(
        bufA, Em0W, Em0b, em, EE, CC, HCC, nullptr, nullptr, nullptr, nullptr, nullptr);
    mma_gemm<64, true, true, false, false><<<dim3(1, EE / 128), 256>>>(
        em, Em1W, Em1b, em2, EE, CC, CC, nullptr, nullptr, nullptr, nullptr, nullptr);
    mma_gemm<64, true, true, false, true><<<dim3(1, EE / 128), 256>>>(
        em2, Em2W, Em2b, out_edge, EE, CC, CC, nullptr, nullptr, nullptr, nullptr, out_edge);

    // 6) node output MLP + residual (fused), then GCN transform
    mma_gemm<64, true, true, false, false><<<dim3(1, ceildiv(NN, 128)), 256>>>(
        agg, Nm0W, Nm0b, n0, NN, CC, HCC, nullptr, nullptr, nullptr, nullptr, nullptr);
    mma_gemm<64, true, true, false, false><<<dim3(1, ceildiv(NN, 128)), 256>>>(
        n0, Nm1W, Nm1b, n1, NN, CC, CC, nullptr, nullptr, nullptr, nullptr, nullptr);
    mma_gemm<64, true, true, false, true><<<dim3(1, ceildiv(NN, 128)), 256>>>(
        n1, Nm2W, Nm2b, n0, NN, CC, CC, nullptr, nullptr, nullptr, nullptr, nodet);
    mma_gemm<64, false, false, false, false><<<dim3(1, ceildiv(NN, 128)), 256>>>(
        n0, gcnW, nullptr, n1, NN, CC, CC, nullptr, nullptr, nullptr, nullptr, nullptr);

    // 7) GCN normalize + aggregate (CSR gather, no atomics)
    k_gcn<<<ceildiv(NN, 8), 256>>>(off, csr, src, deg, n1, gcnb, out_node);
}